// round 7
// baseline (speedup 1.0000x reference)
#include <cuda_runtime.h>
#include <cstdint>

#define TOKENS  4096
#define DMODEL  512
#define VOCAB   128000
#define BM      128
#define BN      128
#define BK      256           /* fp8 elems per half-tile chunk = 256 bytes */
#define NSPLITS 37
#define NTILES_N (VOCAB / BN)   /* 1000 */
#define MTILES   (TOKENS / BM)  /* 32   */

// smem strides (bytes); stride/16 mod 8 == 1 -> 8 consecutive rows hit
// distinct 16B granule phases (conflict-free ldmatrix)
#define ASTRIDE 528   /* 512 + 16 */
#define BSTRIDE 272   /* 256 + 16 */
#define BSTAGE  (128 * BSTRIDE)            /* 34816 */
#define A_BYTES (BM * ASTRIDE)             /* 67584 */
#define RED_OFF (A_BYTES + 4 * BSTAGE)     /* 206848 */
#define SMEM_TOTAL (RED_OFF + 128 * 2 * 4) /* 207872 */

// scales: x*16, W*1024 -> logits scaled 16384x ; exp(l) = 2^(l_s * log2e/16384)
#define SW_X 16.0f
#define SW_W 1024.0f
#define EPI_SCALE 8.805453862847030e-5f   /* log2(e)/16384 */

// ---------------- scratch ----------------
__device__ __align__(16) uint8_t g_X8[TOKENS * DMODEL];
__device__ __align__(16) uint8_t g_W8[(size_t)VOCAB * DMODEL];
__device__ float g_ts[TOKENS];
__device__ float g_sum[NSPLITS * TOKENS];

// ---------------- ptx helpers ----------------
__device__ __forceinline__ float ex2f(float x) {
    float r; asm("ex2.approx.f32 %0, %1;" : "=f"(r) : "f"(x)); return r;
}
__device__ __forceinline__ uint16_t cvt2_e4m3(float lo, float hi) {
    uint16_t r;
    asm("cvt.rn.satfinite.e4m3x2.f32 %0, %1, %2;" : "=h"(r) : "f"(hi), "f"(lo));
    return r;
}
__device__ __forceinline__ void mma_f8(float d[4], const uint32_t a[4],
                                       uint32_t b0, uint32_t b1) {
    asm volatile(
        "mma.sync.aligned.m16n8k32.row.col.f32.e4m3.e4m3.f32 "
        "{%0,%1,%2,%3},{%4,%5,%6,%7},{%8,%9},{%0,%1,%2,%3};"
        : "+f"(d[0]), "+f"(d[1]), "+f"(d[2]), "+f"(d[3])
        : "r"(a[0]), "r"(a[1]), "r"(a[2]), "r"(a[3]), "r"(b0), "r"(b1));
}
#define LDMX4(r0, r1, r2, r3, addr)                                          \
    asm volatile("ldmatrix.sync.aligned.m8n8.x4.shared.b16 {%0,%1,%2,%3},[%4];" \
                 : "=r"(r0), "=r"(r1), "=r"(r2), "=r"(r3) : "r"(addr))

// ---------------- fp8 conversion ----------------
__global__ void convert_w8(const float* __restrict__ src) {
    size_t i = ((size_t)blockIdx.x * blockDim.x + threadIdx.x) * 16;
    const float4* s = reinterpret_cast<const float4*>(src + i);
    float4 f0 = s[0], f1 = s[1], f2 = s[2], f3 = s[3];
    uint32_t u0 = (uint32_t)cvt2_e4m3(f0.x * SW_W, f0.y * SW_W) |
                  ((uint32_t)cvt2_e4m3(f0.z * SW_W, f0.w * SW_W) << 16);
    uint32_t u1 = (uint32_t)cvt2_e4m3(f1.x * SW_W, f1.y * SW_W) |
                  ((uint32_t)cvt2_e4m3(f1.z * SW_W, f1.w * SW_W) << 16);
    uint32_t u2 = (uint32_t)cvt2_e4m3(f2.x * SW_W, f2.y * SW_W) |
                  ((uint32_t)cvt2_e4m3(f2.z * SW_W, f2.w * SW_W) << 16);
    uint32_t u3 = (uint32_t)cvt2_e4m3(f3.x * SW_W, f3.y * SW_W) |
                  ((uint32_t)cvt2_e4m3(f3.z * SW_W, f3.w * SW_W) << 16);
    *reinterpret_cast<uint4*>(g_W8 + i) = make_uint4(u0, u1, u2, u3);
}
__global__ void convert_x8(const float* __restrict__ src) {
    size_t i = ((size_t)blockIdx.x * blockDim.x + threadIdx.x) * 16;
    const float4* s = reinterpret_cast<const float4*>(src + i);
    float4 f0 = s[0], f1 = s[1], f2 = s[2], f3 = s[3];
    uint32_t u0 = (uint32_t)cvt2_e4m3(f0.x * SW_X, f0.y * SW_X) |
                  ((uint32_t)cvt2_e4m3(f0.z * SW_X, f0.w * SW_X) << 16);
    uint32_t u1 = (uint32_t)cvt2_e4m3(f1.x * SW_X, f1.y * SW_X) |
                  ((uint32_t)cvt2_e4m3(f1.z * SW_X, f1.w * SW_X) << 16);
    uint32_t u2 = (uint32_t)cvt2_e4m3(f2.x * SW_X, f2.y * SW_X) |
                  ((uint32_t)cvt2_e4m3(f2.z * SW_X, f2.w * SW_X) << 16);
    uint32_t u3 = (uint32_t)cvt2_e4m3(f3.x * SW_X, f3.y * SW_X) |
                  ((uint32_t)cvt2_e4m3(f3.z * SW_X, f3.w * SW_X) << 16);
    *reinterpret_cast<uint4*>(g_X8 + i) = make_uint4(u0, u1, u2, u3);
}

// ---------------- target score (exact fp32) ----------------
__global__ void target_score_kernel(const float* __restrict__ x,
                                    const float* __restrict__ w,
                                    const int* __restrict__ target) {
    int t = blockIdx.x * 8 + (threadIdx.x >> 5);
    int lane = threadIdx.x & 31;
    if (t >= TOKENS) return;
    int tgt = target[t];
    const float4* xr = reinterpret_cast<const float4*>(x + (size_t)t * DMODEL);
    const float4* wr = reinterpret_cast<const float4*>(w + (size_t)tgt * DMODEL);
    float s = 0.0f;
    #pragma unroll
    for (int i = lane; i < DMODEL / 4; i += 32) {
        float4 a = xr[i]; float4 b = wr[i];
        s += a.x * b.x + a.y * b.y + a.z * b.z + a.w * b.w;
    }
    #pragma unroll
    for (int o = 16; o; o >>= 1) s += __shfl_xor_sync(0xffffffffu, s, o);
    if (lane == 0) g_ts[t] = s;
}

// B half-tile producer: chunk q = (tile q>>1, k-half q&1) = 128 rows x 256 B.
// 2048 16B chunks over 256 threads -> 8 per thread (row += 16 each step).
__device__ __forceinline__ void issue_b(int q, const uint8_t* src_base,
                                        uint32_t dst_base) {
    const uint8_t* src = src_base + (size_t)(q >> 1) * (NSPLITS * BN * DMODEL)
                       + (q & 1) * 256;
    uint32_t dst = dst_base + (uint32_t)((q & 3) * BSTAGE);
    #pragma unroll
    for (int i = 0; i < 8; ++i) {
        asm volatile("cp.async.cg.shared.global [%0], [%1], 16;\n"
                     :: "r"(dst + (uint32_t)(i * 16 * BSTRIDE)),
                        "l"(src + (size_t)i * 16 * DMODEL));
    }
    asm volatile("cp.async.commit_group;\n" ::: "memory");
}

// ---------------- main CE partial kernel (fp8 mma.sync, 4m x 2n warps) ----------------
__global__ void __launch_bounds__(256, 1) ce8_kernel() {
    extern __shared__ char smem[];
    const int tid = threadIdx.x;
    const int lane = tid & 31;
    const int wid = tid >> 5;
    const int wm = wid >> 1;             // 0..3 : m-rows [wm*32, wm*32+32)
    const int wn = wid & 1;              // 0..1 : n-cols [wn*64, wn*64+64)
    const int tile_m = blockIdx.x;
    const int split  = blockIdx.y;

    const uint32_t As_u = (uint32_t)__cvta_generic_to_shared(smem);
    const uint32_t Bs_u = As_u + A_BYTES;
    float* red = reinterpret_cast<float*>(smem + RED_OFF);

    // ---- A tile: 128 x 512 fp8, loaded once ----
    {
        const uint8_t* src = g_X8 + (size_t)tile_m * (BM * DMODEL);
        #pragma unroll
        for (int it = 0; it < 16; ++it) {
            int ch = tid + it * 256;      // 4096 chunks of 16B, 32 per row
            int row = ch >> 5, c16 = ch & 31;
            uint32_t sa = As_u + (uint32_t)(row * ASTRIDE + c16 * 16);
            const void* g = (const void*)(src + (size_t)row * DMODEL + c16 * 16);
            asm volatile("cp.async.cg.shared.global [%0], [%1], 16;\n" :: "r"(sa), "l"(g));
        }
        asm volatile("cp.async.commit_group;\n" ::: "memory");
    }

    const int ntile_cnt = (NTILES_N - 1 - split) / NSPLITS + 1;  // 27 or 28
    const int Q = ntile_cnt * 2;

    // per-thread producer addressing (hoisted)
    const uint8_t* bsrc_base = g_W8 + (size_t)split * (BN * DMODEL)
                             + (size_t)(tid >> 4) * DMODEL + (tid & 15) * 16;
    const uint32_t bdst_base = Bs_u + (uint32_t)((tid >> 4) * BSTRIDE + (tid & 15) * 16);

    issue_b(0, bsrc_base, bdst_base);
    issue_b(1, bsrc_base, bdst_base);
    issue_b(2, bsrc_base, bdst_base);

    float rs[4];                          // (mi, row-half) exp-sum partials
    #pragma unroll
    for (int i = 0; i < 4; ++i) rs[i] = 0.0f;

    float acc[2][8][4];                   // mi x n8-group x 4 regs (m32 x n64)

    // ldmatrix addressing (byte offsets; fp8 = 1 byte)
    const uint32_t a_base = As_u +
        (uint32_t)((wm * 32 + (lane & 15)) * ASTRIDE + ((lane >> 4) & 1) * 16);
    const uint32_t b_lane_off = (uint32_t)(
        (wn * 64 + ((lane >> 4) & 1) * 8 + (lane & 7)) * BSTRIDE +
        ((lane >> 3) & 1) * 16);

    for (int q = 0; q < Q; ++q) {
        int rem = Q - 1 - q;
        if (rem >= 2)      asm volatile("cp.async.wait_group 2;\n" ::: "memory");
        else if (rem == 1) asm volatile("cp.async.wait_group 1;\n" ::: "memory");
        else               asm volatile("cp.async.wait_group 0;\n" ::: "memory");
        __syncthreads();

        const int kc = q & 1;
        if (kc == 0) {
            #pragma unroll
            for (int mi = 0; mi < 2; ++mi)
                #pragma unroll
                for (int g = 0; g < 8; ++g)
                    #pragma unroll
                    for (int j = 0; j < 4; ++j) acc[mi][g][j] = 0.0f;
        }
        const bool fin = (kc == 1);

        const uint32_t bbase = Bs_u + (uint32_t)((q & 3) * BSTAGE) + b_lane_off;
        const uint32_t abase = a_base + (uint32_t)(kc * BK);
        #pragma unroll
        for (int ks = 0; ks < 8; ++ks) {      // eight k32 steps per 256B chunk
            uint32_t a0[4], a1[4];
            LDMX4(a0[0], a0[1], a0[2], a0[3], abase + (uint32_t)(ks * 32));
            LDMX4(a1[0], a1[1], a1[2], a1[3],
                  abase + (uint32_t)(16 * ASTRIDE + ks * 32));
            #pragma unroll
            for (int ng = 0; ng < 4; ++ng) {  // 4 n16 groups (shared by both mi)
                uint32_t b0, b1, b2, b3;
                LDMX4(b0, b1, b2, b3,
                      bbase + (uint32_t)(ng * 16 * BSTRIDE + ks * 32));
                mma_f8(acc[0][ng * 2 + 0], a0, b0, b1);
                mma_f8(acc[0][ng * 2 + 1], a0, b2, b3);
                mma_f8(acc[1][ng * 2 + 0], a1, b0, b1);
                mma_f8(acc[1][ng * 2 + 1], a1, b2, b3);
                if (ks == 7 && fin) {
                    // these 4 acc groups are final: fold exp now so the MUFU
                    // burst overlaps the remaining groups' MMA stream
                    #pragma unroll
                    for (int mi = 0; mi < 2; ++mi) {
                        #pragma unroll
                        for (int g = ng * 2; g < ng * 2 + 2; ++g) {
                            rs[mi * 2 + 0] += ex2f(acc[mi][g][0] * EPI_SCALE)
                                            + ex2f(acc[mi][g][1] * EPI_SCALE);
                            rs[mi * 2 + 1] += ex2f(acc[mi][g][2] * EPI_SCALE)
                                            + ex2f(acc[mi][g][3] * EPI_SCALE);
                        }
                    }
                }
            }
        }

        if (q + 3 < Q) issue_b(q + 3, bsrc_base, bdst_base);
    }

    // ---- reduce: quad (n within warp) -> smem (across the 2 n-warps) ----
    #pragma unroll
    for (int i = 0; i < 4; ++i) {
        rs[i] += __shfl_xor_sync(0xffffffffu, rs[i], 1);
        rs[i] += __shfl_xor_sync(0xffffffffu, rs[i], 2);
    }
    __syncthreads();
    if ((lane & 3) == 0) {
        int g = lane >> 2;               // 0..7
        #pragma unroll
        for (int mi = 0; mi < 2; ++mi) {
            int row0 = wm * 32 + mi * 16 + g;
            red[row0 * 2 + wn] = rs[mi * 2 + 0];
            red[(row0 + 8) * 2 + wn] = rs[mi * 2 + 1];
        }
    }
    __syncthreads();
    if (tid < BM) {
        g_sum[split * TOKENS + tile_m * BM + tid] = red[tid * 2] + red[tid * 2 + 1];
    }
}

// ---------------- final loss reduce ----------------
__global__ void loss_kernel(float* __restrict__ out) {
    __shared__ float sm[256];
    float acc = 0.0f;
    for (int t = threadIdx.x; t < TOKENS; t += 256) {
        float S = 0.0f;
        #pragma unroll
        for (int s = 0; s < NSPLITS; ++s) S += g_sum[s * TOKENS + t];
        acc += logf(S) - g_ts[t];
    }
    sm[threadIdx.x] = acc;
    __syncthreads();
    #pragma unroll
    for (int o = 128; o; o >>= 1) {
        if (threadIdx.x < o) sm[threadIdx.x] += sm[threadIdx.x + o];
        __syncthreads();
    }
    if (threadIdx.x == 0) out[0] = sm[0];
}

// ---------------- launch ----------------
extern "C" void kernel_launch(void* const* d_in, const int* in_sizes, int n_in,
                              void* d_out, int out_size) {
    const float* x = (const float*)d_in[0];
    const float* w = (const float*)d_in[1];
    const int* target = (const int*)d_in[2];
    float* out = (float*)d_out;
    (void)in_sizes; (void)n_in; (void)out_size;

    cudaFuncSetAttribute(ce8_kernel, cudaFuncAttributeMaxDynamicSharedMemorySize,
                         SMEM_TOTAL);

    convert_w8<<<16000, 256>>>(w);                    // 16000*256*16 = 65,536,000
    convert_x8<<<512, 256>>>(x);                      // 512*256*16  =  2,097,152
    target_score_kernel<<<TOKENS / 8, 256>>>(x, w, target);
    ce8_kernel<<<dim3(MTILES, NSPLITS), 256, SMEM_TOTAL>>>();
    loss_kernel<<<1, 256>>>(out);
}

// round 8
// speedup vs baseline: 1.2462x; 1.2462x over previous
#include <cuda_runtime.h>
#include <cstdint>

#define TOKENS  4096
#define DMODEL  512
#define VOCAB   128000
#define BM      256
#define BN      128
#define BK      128           /* fp8 elems per k-chunk = 128 bytes */
#define NSPLITS 37
#define NTILES_N (VOCAB / BN)   /* 1000 */
#define MTILES   (TOKENS / BM)  /* 16   */

// smem strides (bytes); stride/16 mod 8 == 1 -> conflict-free ldmatrix rows
#define ASTRIDE 528   /* 512 + 16 */
#define BSTRIDE 144   /* 128 + 16 */
#define BSTAGE  (128 * BSTRIDE)            /* 18432 */
#define A_BYTES (BM * ASTRIDE)             /* 135168 */
#define RED_OFF (A_BYTES + 4 * BSTAGE)     /* 208896 */
#define SMEM_TOTAL (RED_OFF + BM * 2 * 4)  /* 210944 */

// scales: x*16, W*1024 -> logits scaled 16384x ; exp(l) = 2^(l_s * log2e/16384)
#define SW_X 16.0f
#define SW_W 1024.0f
#define EPI_SCALE 8.805453862847030e-5f   /* log2(e)/16384 */

// ---------------- scratch ----------------
__device__ __align__(16) uint8_t g_X8[TOKENS * DMODEL];
__device__ __align__(16) uint8_t g_W8[(size_t)VOCAB * DMODEL];
__device__ float g_ts[TOKENS];
__device__ float g_sum[NSPLITS * TOKENS];

// ---------------- ptx helpers ----------------
__device__ __forceinline__ float ex2f(float x) {
    float r; asm("ex2.approx.f32 %0, %1;" : "=f"(r) : "f"(x)); return r;
}
__device__ __forceinline__ uint16_t cvt2_e4m3(float lo, float hi) {
    uint16_t r;
    asm("cvt.rn.satfinite.e4m3x2.f32 %0, %1, %2;" : "=h"(r) : "f"(hi), "f"(lo));
    return r;
}
__device__ __forceinline__ void mma_f8(float d[4], const uint32_t a[4],
                                       uint32_t b0, uint32_t b1) {
    asm volatile(
        "mma.sync.aligned.m16n8k32.row.col.f32.e4m3.e4m3.f32 "
        "{%0,%1,%2,%3},{%4,%5,%6,%7},{%8,%9},{%0,%1,%2,%3};"
        : "+f"(d[0]), "+f"(d[1]), "+f"(d[2]), "+f"(d[3])
        : "r"(a[0]), "r"(a[1]), "r"(a[2]), "r"(a[3]), "r"(b0), "r"(b1));
}
#define LDMX4(r0, r1, r2, r3, addr)                                          \
    asm volatile("ldmatrix.sync.aligned.m8n8.x4.shared.b16 {%0,%1,%2,%3},[%4];" \
                 : "=r"(r0), "=r"(r1), "=r"(r2), "=r"(r3) : "r"(addr))

// ---------------- fp8 conversion ----------------
__global__ void convert_w8(const float* __restrict__ src) {
    size_t i = ((size_t)blockIdx.x * blockDim.x + threadIdx.x) * 16;
    const float4* s = reinterpret_cast<const float4*>(src + i);
    float4 f0 = s[0], f1 = s[1], f2 = s[2], f3 = s[3];
    uint32_t u0 = (uint32_t)cvt2_e4m3(f0.x * SW_W, f0.y * SW_W) |
                  ((uint32_t)cvt2_e4m3(f0.z * SW_W, f0.w * SW_W) << 16);
    uint32_t u1 = (uint32_t)cvt2_e4m3(f1.x * SW_W, f1.y * SW_W) |
                  ((uint32_t)cvt2_e4m3(f1.z * SW_W, f1.w * SW_W) << 16);
    uint32_t u2 = (uint32_t)cvt2_e4m3(f2.x * SW_W, f2.y * SW_W) |
                  ((uint32_t)cvt2_e4m3(f2.z * SW_W, f2.w * SW_W) << 16);
    uint32_t u3 = (uint32_t)cvt2_e4m3(f3.x * SW_W, f3.y * SW_W) |
                  ((uint32_t)cvt2_e4m3(f3.z * SW_W, f3.w * SW_W) << 16);
    *reinterpret_cast<uint4*>(g_W8 + i) = make_uint4(u0, u1, u2, u3);
}
__global__ void convert_x8(const float* __restrict__ src) {
    size_t i = ((size_t)blockIdx.x * blockDim.x + threadIdx.x) * 16;
    const float4* s = reinterpret_cast<const float4*>(src + i);
    float4 f0 = s[0], f1 = s[1], f2 = s[2], f3 = s[3];
    uint32_t u0 = (uint32_t)cvt2_e4m3(f0.x * SW_X, f0.y * SW_X) |
                  ((uint32_t)cvt2_e4m3(f0.z * SW_X, f0.w * SW_X) << 16);
    uint32_t u1 = (uint32_t)cvt2_e4m3(f1.x * SW_X, f1.y * SW_X) |
                  ((uint32_t)cvt2_e4m3(f1.z * SW_X, f1.w * SW_X) << 16);
    uint32_t u2 = (uint32_t)cvt2_e4m3(f2.x * SW_X, f2.y * SW_X) |
                  ((uint32_t)cvt2_e4m3(f2.z * SW_X, f2.w * SW_X) << 16);
    uint32_t u3 = (uint32_t)cvt2_e4m3(f3.x * SW_X, f3.y * SW_X) |
                  ((uint32_t)cvt2_e4m3(f3.z * SW_X, f3.w * SW_X) << 16);
    *reinterpret_cast<uint4*>(g_X8 + i) = make_uint4(u0, u1, u2, u3);
}

// ---------------- target score (exact fp32) ----------------
__global__ void target_score_kernel(const float* __restrict__ x,
                                    const float* __restrict__ w,
                                    const int* __restrict__ target) {
    int t = blockIdx.x * 8 + (threadIdx.x >> 5);
    int lane = threadIdx.x & 31;
    if (t >= TOKENS) return;
    int tgt = target[t];
    const float4* xr = reinterpret_cast<const float4*>(x + (size_t)t * DMODEL);
    const float4* wr = reinterpret_cast<const float4*>(w + (size_t)tgt * DMODEL);
    float s = 0.0f;
    #pragma unroll
    for (int i = lane; i < DMODEL / 4; i += 32) {
        float4 a = xr[i]; float4 b = wr[i];
        s += a.x * b.x + a.y * b.y + a.z * b.z + a.w * b.w;
    }
    #pragma unroll
    for (int o = 16; o; o >>= 1) s += __shfl_xor_sync(0xffffffffu, s, o);
    if (lane == 0) g_ts[t] = s;
}

// B-chunk producer: one (n-tile, k-chunk) = 128 rows x 128 B via cp.async.
// 1024 chunks of 16B over 512 threads -> 2 per thread (rows tid>>3 and 64+tid>>3).
__device__ __forceinline__ void issue_b(int q, const uint8_t* src_base,
                                        uint32_t dst_base) {
    int nt_idx = q >> 2;                     // vocab tile index within split
    int kc = q & 3;
    const uint8_t* src = src_base + (size_t)nt_idx * (NSPLITS * BN * DMODEL) + kc * BK;
    uint32_t dst = dst_base + (uint32_t)((q & 3) * BSTAGE);
    asm volatile("cp.async.cg.shared.global [%0], [%1], 16;\n"
                 :: "r"(dst), "l"(src));
    asm volatile("cp.async.cg.shared.global [%0], [%1], 16;\n"
                 :: "r"(dst + 64 * BSTRIDE), "l"(src + (size_t)64 * DMODEL));
    asm volatile("cp.async.commit_group;\n" ::: "memory");
}

// ---------------- main CE partial kernel (fp8 mma.sync, 8m x 2n warps, 512 thr) ----
__global__ void __launch_bounds__(512, 1) ce8_kernel() {
    extern __shared__ char smem[];
    const int tid = threadIdx.x;
    const int lane = tid & 31;
    const int wid = tid >> 5;
    const int wm = wid >> 1;             // 0..7 : m-rows [wm*32, wm*32+32)
    const int wn = wid & 1;              // 0..1 : n-cols [wn*64, wn*64+64)
    const int tile_m = blockIdx.x;
    const int split  = blockIdx.y;

    const uint32_t As_u = (uint32_t)__cvta_generic_to_shared(smem);
    const uint32_t Bs_u = As_u + A_BYTES;
    float* red = reinterpret_cast<float*>(smem + RED_OFF);

    // ---- A tile: 256 x 512 fp8, loaded once ----
    {
        const uint8_t* src = g_X8 + (size_t)tile_m * (BM * DMODEL);
        #pragma unroll
        for (int it = 0; it < 16; ++it) {
            int ch = tid + it * 512;      // 8192 chunks of 16B, 32 per row
            int row = ch >> 5, c16 = ch & 31;
            uint32_t sa = As_u + (uint32_t)(row * ASTRIDE + c16 * 16);
            const void* g = (const void*)(src + (size_t)row * DMODEL + c16 * 16);
            asm volatile("cp.async.cg.shared.global [%0], [%1], 16;\n" :: "r"(sa), "l"(g));
        }
        asm volatile("cp.async.commit_group;\n" ::: "memory");
    }

    const int ntile_cnt = (NTILES_N - 1 - split) / NSPLITS + 1;  // 27 or 28
    const int Q = ntile_cnt * 4;

    // per-thread producer addressing (hoisted)
    const uint8_t* bsrc_base = g_W8 + (size_t)split * (BN * DMODEL)
                             + (size_t)(tid >> 3) * DMODEL + (tid & 7) * 16;
    const uint32_t bdst_base = Bs_u + (uint32_t)((tid >> 3) * BSTRIDE + (tid & 7) * 16);

    issue_b(0, bsrc_base, bdst_base);
    issue_b(1, bsrc_base, bdst_base);
    issue_b(2, bsrc_base, bdst_base);

    float rs[4];                          // (mi, row-half) exp-sum partials
    #pragma unroll
    for (int i = 0; i < 4; ++i) rs[i] = 0.0f;

    float acc[2][8][4];                   // mi x n8-group x 4 regs (m32 x n64)

    // ldmatrix addressing (byte offsets; fp8 = 1 byte)
    const uint32_t a_base = As_u +
        (uint32_t)((wm * 32 + (lane & 15)) * ASTRIDE + ((lane >> 4) & 1) * 16);
    const uint32_t b_lane_off = (uint32_t)(
        (wn * 64 + ((lane >> 4) & 1) * 8 + (lane & 7)) * BSTRIDE +
        ((lane >> 3) & 1) * 16);

    for (int q = 0; q < Q; ++q) {
        int rem = Q - 1 - q;
        if (rem >= 2)      asm volatile("cp.async.wait_group 2;\n" ::: "memory");
        else if (rem == 1) asm volatile("cp.async.wait_group 1;\n" ::: "memory");
        else               asm volatile("cp.async.wait_group 0;\n" ::: "memory");
        __syncthreads();

        const int kc = q & 3;
        if (kc == 0) {
            #pragma unroll
            for (int mi = 0; mi < 2; ++mi)
                #pragma unroll
                for (int g = 0; g < 8; ++g)
                    #pragma unroll
                    for (int j = 0; j < 4; ++j) acc[mi][g][j] = 0.0f;
        }
        const bool fin = (kc == 3);

        const uint32_t bbase = Bs_u + (uint32_t)((q & 3) * BSTAGE) + b_lane_off;
        const uint32_t abase = a_base + (uint32_t)(kc * BK);
        #pragma unroll
        for (int ks = 0; ks < 4; ++ks) {      // four k32 steps per 128B chunk
            uint32_t a0[4], a1[4];
            LDMX4(a0[0], a0[1], a0[2], a0[3], abase + (uint32_t)(ks * 32));
            LDMX4(a1[0], a1[1], a1[2], a1[3],
                  abase + (uint32_t)(16 * ASTRIDE + ks * 32));
            #pragma unroll
            for (int ng = 0; ng < 4; ++ng) {  // 4 n16 groups (shared by both mi)
                uint32_t b0, b1, b2, b3;
                LDMX4(b0, b1, b2, b3,
                      bbase + (uint32_t)(ng * 16 * BSTRIDE + ks * 32));
                mma_f8(acc[0][ng * 2 + 0], a0, b0, b1);
                mma_f8(acc[0][ng * 2 + 1], a0, b2, b3);
                mma_f8(acc[1][ng * 2 + 0], a1, b0, b1);
                mma_f8(acc[1][ng * 2 + 1], a1, b2, b3);
                if (ks == 3 && fin) {
                    // these acc groups are final: fold exp now so the MUFU
                    // burst overlaps the remaining groups' MMA stream
                    #pragma unroll
                    for (int mi = 0; mi < 2; ++mi) {
                        #pragma unroll
                        for (int g = ng * 2; g < ng * 2 + 2; ++g) {
                            rs[mi * 2 + 0] += ex2f(acc[mi][g][0] * EPI_SCALE)
                                            + ex2f(acc[mi][g][1] * EPI_SCALE);
                            rs[mi * 2 + 1] += ex2f(acc[mi][g][2] * EPI_SCALE)
                                            + ex2f(acc[mi][g][3] * EPI_SCALE);
                        }
                    }
                }
            }
        }

        if (q + 3 < Q) issue_b(q + 3, bsrc_base, bdst_base);
    }

    // ---- reduce: quad (n within warp) -> smem (across the 2 n-warps) ----
    #pragma unroll
    for (int i = 0; i < 4; ++i) {
        rs[i] += __shfl_xor_sync(0xffffffffu, rs[i], 1);
        rs[i] += __shfl_xor_sync(0xffffffffu, rs[i], 2);
    }
    __syncthreads();
    if ((lane & 3) == 0) {
        int g = lane >> 2;               // 0..7
        #pragma unroll
        for (int mi = 0; mi < 2; ++mi) {
            int row0 = wm * 32 + mi * 16 + g;
            red[row0 * 2 + wn] = rs[mi * 2 + 0];
            red[(row0 + 8) * 2 + wn] = rs[mi * 2 + 1];
        }
    }
    __syncthreads();
    if (tid < BM) {
        g_sum[split * TOKENS + tile_m * BM + tid] = red[tid * 2] + red[tid * 2 + 1];
    }
}

// ---------------- final loss reduce ----------------
__global__ void loss_kernel(float* __restrict__ out) {
    __shared__ float sm[256];
    float acc = 0.0f;
    for (int t = threadIdx.x; t < TOKENS; t += 256) {
        float S = 0.0f;
        #pragma unroll
        for (int s = 0; s < NSPLITS; ++s) S += g_sum[s * TOKENS + t];
        acc += logf(S) - g_ts[t];
    }
    sm[threadIdx.x] = acc;
    __syncthreads();
    #pragma unroll
    for (int o = 128; o; o >>= 1) {
        if (threadIdx.x < o) sm[threadIdx.x] += sm[threadIdx.x + o];
        __syncthreads();
    }
    if (threadIdx.x == 0) out[0] = sm[0];
}

// ---------------- launch ----------------
extern "C" void kernel_launch(void* const* d_in, const int* in_sizes, int n_in,
                              void* d_out, int out_size) {
    const float* x = (const float*)d_in[0];
    const float* w = (const float*)d_in[1];
    const int* target = (const int*)d_in[2];
    float* out = (float*)d_out;
    (void)in_sizes; (void)n_in; (void)out_size;

    cudaFuncSetAttribute(ce8_kernel, cudaFuncAttributeMaxDynamicSharedMemorySize,
                         SMEM_TOTAL);

    convert_w8<<<16000, 256>>>(w);                    // 16000*256*16 = 65,536,000
    convert_x8<<<512, 256>>>(x);                      // 512*256*16  =  2,097,152
    target_score_kernel<<<TOKENS / 8, 256>>>(x, w, target);
    ce8_kernel<<<dim3(MTILES, NSPLITS), 512, SMEM_TOTAL>>>();
    loss_kernel<<<1, 256>>>(out);
}

// round 9
// speedup vs baseline: 1.3382x; 1.0739x over previous
#include <cuda_runtime.h>
#include <cuda_fp16.h>
#include <cstdint>

#define TOKENS  4096
#define DMODEL  512
#define VOCAB   128000
#define BM      256
#define BN      128
#define BK      128           /* fp8 elems per k-chunk = 128 bytes */
#define NSPLITS 37
#define NTILES_N (VOCAB / BN)   /* 1000 */
#define MTILES   (TOKENS / BM)  /* 16   */

// smem strides (bytes); stride/16 mod 8 == 1 -> conflict-free ldmatrix rows
#define ASTRIDE 528   /* 512 + 16 */
#define BSTRIDE 144   /* 128 + 16 */
#define BSTAGE  (128 * BSTRIDE)            /* 18432 */
#define A_BYTES (BM * ASTRIDE)             /* 135168 */
#define RED_OFF (A_BYTES + 4 * BSTAGE)     /* 208896 */
#define SMEM_TOTAL (RED_OFF + BM * 2 * 4)  /* 210944 */

// scales: x*16, W*256 -> logits scaled 4096x (fp16-acc safe: |logit|<~10k)
// exp(l) = 2^(l_s * log2e / 4096)
#define SW_X 16.0f
#define SW_W 256.0f
#define EPI_SCALE 3.522181545138923e-4f   /* log2(e)/4096 */

// ---------------- scratch ----------------
__device__ __align__(16) uint8_t g_X8[TOKENS * DMODEL];
__device__ __align__(16) uint8_t g_W8[(size_t)VOCAB * DMODEL];
__device__ float g_ts[TOKENS];
__device__ float g_sum[NSPLITS * TOKENS];

// ---------------- ptx helpers ----------------
__device__ __forceinline__ float ex2f(float x) {
    float r; asm("ex2.approx.f32 %0, %1;" : "=f"(r) : "f"(x)); return r;
}
__device__ __forceinline__ uint16_t cvt2_e4m3(float lo, float hi) {
    uint16_t r;
    asm("cvt.rn.satfinite.e4m3x2.f32 %0, %1, %2;" : "=h"(r) : "f"(hi), "f"(lo));
    return r;
}
// fp8 x fp8 -> fp16 accumulators (full-rate legacy-tensor variant)
__device__ __forceinline__ void mma_f8h(uint32_t d[2], const uint32_t a[4],
                                        uint32_t b0, uint32_t b1) {
    asm volatile(
        "mma.sync.aligned.m16n8k32.row.col.f16.e4m3.e4m3.f16 "
        "{%0,%1},{%2,%3,%4,%5},{%6,%7},{%0,%1};"
        : "+r"(d[0]), "+r"(d[1])
        : "r"(a[0]), "r"(a[1]), "r"(a[2]), "r"(a[3]), "r"(b0), "r"(b1));
}
#define LDMX4(r0, r1, r2, r3, addr)                                          \
    asm volatile("ldmatrix.sync.aligned.m8n8.x4.shared.b16 {%0,%1,%2,%3},[%4];" \
                 : "=r"(r0), "=r"(r1), "=r"(r2), "=r"(r3) : "r"(addr))

// ---------------- fp8 conversion ----------------
__global__ void convert_w8(const float* __restrict__ src) {
    size_t i = ((size_t)blockIdx.x * blockDim.x + threadIdx.x) * 16;
    const float4* s = reinterpret_cast<const float4*>(src + i);
    float4 f0 = s[0], f1 = s[1], f2 = s[2], f3 = s[3];
    uint32_t u0 = (uint32_t)cvt2_e4m3(f0.x * SW_W, f0.y * SW_W) |
                  ((uint32_t)cvt2_e4m3(f0.z * SW_W, f0.w * SW_W) << 16);
    uint32_t u1 = (uint32_t)cvt2_e4m3(f1.x * SW_W, f1.y * SW_W) |
                  ((uint32_t)cvt2_e4m3(f1.z * SW_W, f1.w * SW_W) << 16);
    uint32_t u2 = (uint32_t)cvt2_e4m3(f2.x * SW_W, f2.y * SW_W) |
                  ((uint32_t)cvt2_e4m3(f2.z * SW_W, f2.w * SW_W) << 16);
    uint32_t u3 = (uint32_t)cvt2_e4m3(f3.x * SW_W, f3.y * SW_W) |
                  ((uint32_t)cvt2_e4m3(f3.z * SW_W, f3.w * SW_W) << 16);
    *reinterpret_cast<uint4*>(g_W8 + i) = make_uint4(u0, u1, u2, u3);
}
__global__ void convert_x8(const float* __restrict__ src) {
    size_t i = ((size_t)blockIdx.x * blockDim.x + threadIdx.x) * 16;
    const float4* s = reinterpret_cast<const float4*>(src + i);
    float4 f0 = s[0], f1 = s[1], f2 = s[2], f3 = s[3];
    uint32_t u0 = (uint32_t)cvt2_e4m3(f0.x * SW_X, f0.y * SW_X) |
                  ((uint32_t)cvt2_e4m3(f0.z * SW_X, f0.w * SW_X) << 16);
    uint32_t u1 = (uint32_t)cvt2_e4m3(f1.x * SW_X, f1.y * SW_X) |
                  ((uint32_t)cvt2_e4m3(f1.z * SW_X, f1.w * SW_X) << 16);
    uint32_t u2 = (uint32_t)cvt2_e4m3(f2.x * SW_X, f2.y * SW_X) |
                  ((uint32_t)cvt2_e4m3(f2.z * SW_X, f2.w * SW_X) << 16);
    uint32_t u3 = (uint32_t)cvt2_e4m3(f3.x * SW_X, f3.y * SW_X) |
                  ((uint32_t)cvt2_e4m3(f3.z * SW_X, f3.w * SW_X) << 16);
    *reinterpret_cast<uint4*>(g_X8 + i) = make_uint4(u0, u1, u2, u3);
}

// ---------------- target score (exact fp32) ----------------
__global__ void target_score_kernel(const float* __restrict__ x,
                                    const float* __restrict__ w,
                                    const int* __restrict__ target) {
    int t = blockIdx.x * 8 + (threadIdx.x >> 5);
    int lane = threadIdx.x & 31;
    if (t >= TOKENS) return;
    int tgt = target[t];
    const float4* xr = reinterpret_cast<const float4*>(x + (size_t)t * DMODEL);
    const float4* wr = reinterpret_cast<const float4*>(w + (size_t)tgt * DMODEL);
    float s = 0.0f;
    #pragma unroll
    for (int i = lane; i < DMODEL / 4; i += 32) {
        float4 a = xr[i]; float4 b = wr[i];
        s += a.x * b.x + a.y * b.y + a.z * b.z + a.w * b.w;
    }
    #pragma unroll
    for (int o = 16; o; o >>= 1) s += __shfl_xor_sync(0xffffffffu, s, o);
    if (lane == 0) g_ts[t] = s;
}

// B-chunk producer: one (n-tile, k-chunk) = 128 rows x 128 B via cp.async.
// 1024 chunks of 16B over 512 threads -> 2 per thread (rows tid>>3 and 64+tid>>3).
__device__ __forceinline__ void issue_b(int q, const uint8_t* src_base,
                                        uint32_t dst_base) {
    int nt_idx = q >> 2;                     // vocab tile index within split
    int kc = q & 3;
    const uint8_t* src = src_base + (size_t)nt_idx * (NSPLITS * BN * DMODEL) + kc * BK;
    uint32_t dst = dst_base + (uint32_t)((q & 3) * BSTAGE);
    asm volatile("cp.async.cg.shared.global [%0], [%1], 16;\n"
                 :: "r"(dst), "l"(src));
    asm volatile("cp.async.cg.shared.global [%0], [%1], 16;\n"
                 :: "r"(dst + 64 * BSTRIDE), "l"(src + (size_t)64 * DMODEL));
    asm volatile("cp.async.commit_group;\n" ::: "memory");
}

// ---------------- main CE partial kernel (fp8 mma.sync f16-acc, 8m x 2n, 512 thr) --
__global__ void __launch_bounds__(512, 1) ce8_kernel() {
    extern __shared__ char smem[];
    const int tid = threadIdx.x;
    const int lane = tid & 31;
    const int wid = tid >> 5;
    const int wm = wid >> 1;             // 0..7 : m-rows [wm*32, wm*32+32)
    const int wn = wid & 1;              // 0..1 : n-cols [wn*64, wn*64+64)
    const int tile_m = blockIdx.x;
    const int split  = blockIdx.y;

    const uint32_t As_u = (uint32_t)__cvta_generic_to_shared(smem);
    const uint32_t Bs_u = As_u + A_BYTES;
    float* red = reinterpret_cast<float*>(smem + RED_OFF);

    // ---- A tile: 256 x 512 fp8, loaded once ----
    {
        const uint8_t* src = g_X8 + (size_t)tile_m * (BM * DMODEL);
        #pragma unroll
        for (int it = 0; it < 16; ++it) {
            int ch = tid + it * 512;      // 8192 chunks of 16B, 32 per row
            int row = ch >> 5, c16 = ch & 31;
            uint32_t sa = As_u + (uint32_t)(row * ASTRIDE + c16 * 16);
            const void* g = (const void*)(src + (size_t)row * DMODEL + c16 * 16);
            asm volatile("cp.async.cg.shared.global [%0], [%1], 16;\n" :: "r"(sa), "l"(g));
        }
        asm volatile("cp.async.commit_group;\n" ::: "memory");
    }

    const int ntile_cnt = (NTILES_N - 1 - split) / NSPLITS + 1;  // 27 or 28
    const int Q = ntile_cnt * 4;

    // per-thread producer addressing (hoisted)
    const uint8_t* bsrc_base = g_W8 + (size_t)split * (BN * DMODEL)
                             + (size_t)(tid >> 3) * DMODEL + (tid & 7) * 16;
    const uint32_t bdst_base = Bs_u + (uint32_t)((tid >> 3) * BSTRIDE + (tid & 7) * 16);

    issue_b(0, bsrc_base, bdst_base);
    issue_b(1, bsrc_base, bdst_base);
    issue_b(2, bsrc_base, bdst_base);

    float rs[4];                          // (mi, row-half) exp-sum partials
    #pragma unroll
    for (int i = 0; i < 4; ++i) rs[i] = 0.0f;

    uint32_t acc[2][8][2];                // mi x n8-group x 2 f16x2 regs (m32 x n64)

    // ldmatrix addressing (byte offsets; fp8 = 1 byte)
    const uint32_t a_base = As_u +
        (uint32_t)((wm * 32 + (lane & 15)) * ASTRIDE + ((lane >> 4) & 1) * 16);
    const uint32_t b_lane_off = (uint32_t)(
        (wn * 64 + ((lane >> 4) & 1) * 8 + (lane & 7)) * BSTRIDE +
        ((lane >> 3) & 1) * 16);

    for (int q = 0; q < Q; ++q) {
        int rem = Q - 1 - q;
        if (rem >= 2)      asm volatile("cp.async.wait_group 2;\n" ::: "memory");
        else if (rem == 1) asm volatile("cp.async.wait_group 1;\n" ::: "memory");
        else               asm volatile("cp.async.wait_group 0;\n" ::: "memory");
        __syncthreads();

        const int kc = q & 3;
        if (kc == 0) {
            #pragma unroll
            for (int mi = 0; mi < 2; ++mi)
                #pragma unroll
                for (int g = 0; g < 8; ++g) {
                    acc[mi][g][0] = 0u; acc[mi][g][1] = 0u;
                }
        }
        const bool fin = (kc == 3);

        const uint32_t bbase = Bs_u + (uint32_t)((q & 3) * BSTAGE) + b_lane_off;
        const uint32_t abase = a_base + (uint32_t)(kc * BK);
        #pragma unroll
        for (int ks = 0; ks < 4; ++ks) {      // four k32 steps per 128B chunk
            uint32_t a0[4], a1[4];
            LDMX4(a0[0], a0[1], a0[2], a0[3], abase + (uint32_t)(ks * 32));
            LDMX4(a1[0], a1[1], a1[2], a1[3],
                  abase + (uint32_t)(16 * ASTRIDE + ks * 32));
            #pragma unroll
            for (int ng = 0; ng < 4; ++ng) {  // 4 n16 groups (shared by both mi)
                uint32_t b0, b1, b2, b3;
                LDMX4(b0, b1, b2, b3,
                      bbase + (uint32_t)(ng * 16 * BSTRIDE + ks * 32));
                mma_f8h(acc[0][ng * 2 + 0], a0, b0, b1);
                mma_f8h(acc[0][ng * 2 + 1], a0, b2, b3);
                mma_f8h(acc[1][ng * 2 + 0], a1, b0, b1);
                mma_f8h(acc[1][ng * 2 + 1], a1, b2, b3);
                if (ks == 3 && fin) {
                    // these acc groups are final: fold exp now so the MUFU
                    // burst overlaps the remaining groups' MMA stream
                    #pragma unroll
                    for (int mi = 0; mi < 2; ++mi) {
                        #pragma unroll
                        for (int g = ng * 2; g < ng * 2 + 2; ++g) {
                            float2 v0 = __half22float2(
                                *reinterpret_cast<__half2*>(&acc[mi][g][0]));
                            float2 v1 = __half22float2(
                                *reinterpret_cast<__half2*>(&acc[mi][g][1]));
                            rs[mi * 2 + 0] += ex2f(v0.x * EPI_SCALE)
                                            + ex2f(v0.y * EPI_SCALE);
                            rs[mi * 2 + 1] += ex2f(v1.x * EPI_SCALE)
                                            + ex2f(v1.y * EPI_SCALE);
                        }
                    }
                }
            }
        }

        if (q + 3 < Q) issue_b(q + 3, bsrc_base, bdst_base);
    }

    // ---- reduce: quad (n within warp) -> smem (across the 2 n-warps) ----
    #pragma unroll
    for (int i = 0; i < 4; ++i) {
        rs[i] += __shfl_xor_sync(0xffffffffu, rs[i], 1);
        rs[i] += __shfl_xor_sync(0xffffffffu, rs[i], 2);
    }
    __syncthreads();
    if ((lane & 3) == 0) {
        int g = lane >> 2;               // 0..7
        #pragma unroll
        for (int mi = 0; mi < 2; ++mi) {
            int row0 = wm * 32 + mi * 16 + g;
            red[row0 * 2 + wn] = rs[mi * 2 + 0];
            red[(row0 + 8) * 2 + wn] = rs[mi * 2 + 1];
        }
    }
    __syncthreads();
    if (tid < BM) {
        g_sum[split * TOKENS + tile_m * BM + tid] = red[tid * 2] + red[tid * 2 + 1];
    }
}

// ---------------- final loss reduce ----------------
__global__ void loss_kernel(float* __restrict__ out) {
    __shared__ float sm[256];
    float acc = 0.0f;
    for (int t = threadIdx.x; t < TOKENS; t += 256) {
        float S = 0.0f;
        #pragma unroll
        for (int s = 0; s < NSPLITS; ++s) S += g_sum[s * TOKENS + t];
        acc += logf(S) - g_ts[t];
    }
    sm[threadIdx.x] = acc;
    __syncthreads();
    #pragma unroll
    for (int o = 128; o; o >>= 1) {
        if (threadIdx.x < o) sm[threadIdx.x] += sm[threadIdx.x + o];
        __syncthreads();
    }
    if (threadIdx.x == 0) out[0] = sm[0];
}

// ---------------- launch ----------------
extern "C" void kernel_launch(void* const* d_in, const int* in_sizes, int n_in,
                              void* d_out, int out_size) {
    const float* x = (const float*)d_in[0];
    const float* w = (const float*)d_in[1];
    const int* target = (const int*)d_in[2];
    float* out = (float*)d_out;
    (void)in_sizes; (void)n_in; (void)out_size;

    cudaFuncSetAttribute(ce8_kernel, cudaFuncAttributeMaxDynamicSharedMemorySize,
                         SMEM_TOTAL);

    convert_w8<<<16000, 256>>>(w);                    // 16000*256*16 = 65,536,000
    convert_x8<<<512, 256>>>(x);                      // 512*256*16  =  2,097,152
    target_score_kernel<<<TOKENS / 8, 256>>>(x, w, target);
    ce8_kernel<<<dim3(MTILES, NSPLITS), 512, SMEM_TOTAL>>>();
    loss_kernel<<<1, 256>>>(out);
}

// round 10
// speedup vs baseline: 1.3756x; 1.0279x over previous
#include <cuda_runtime.h>
#include <cuda_fp16.h>
#include <cstdint>

#define TOKENS  4096
#define DMODEL  512
#define VOCAB   128000
#define BM      256
#define BN      128
#define BK      128           /* fp8 elems per k-chunk = 128 bytes */
#define NSPLITS 37
#define NTILES_N (VOCAB / BN)   /* 1000 */
#define MTILES   (TOKENS / BM)  /* 16   */
#define NSTAGE  6

// swizzled layouts, no padding. phys = row*rowbytes + ((col16*16) ^ ((row&7)<<4))
#define BSTAGE  (128 * 128)                      /* 16384 */
#define A_BYTES (BM * 512)                       /* 131072 */
#define RED_OFF (A_BYTES + NSTAGE * BSTAGE)      /* 229376 */
#define SMEM_TOTAL (RED_OFF + BM * 2 * 4)        /* 231424 <= 232448 cap */

// scales: x*16, W*256 -> logits scaled 4096x (fp16-acc safe)
#define SW_X 16.0f
#define SW_W 256.0f
#define EPI_SCALE 3.522181545138923e-4f   /* log2(e)/4096 */

// ---------------- scratch ----------------
__device__ __align__(16) uint8_t g_X8[TOKENS * DMODEL];
__device__ __align__(16) uint8_t g_W8[(size_t)VOCAB * DMODEL];
__device__ float g_ts[TOKENS];
__device__ float g_sum[NSPLITS * TOKENS];

// ---------------- ptx helpers ----------------
__device__ __forceinline__ float ex2f(float x) {
    float r; asm("ex2.approx.f32 %0, %1;" : "=f"(r) : "f"(x)); return r;
}
__device__ __forceinline__ uint16_t cvt2_e4m3(float lo, float hi) {
    uint16_t r;
    asm("cvt.rn.satfinite.e4m3x2.f32 %0, %1, %2;" : "=h"(r) : "f"(hi), "f"(lo));
    return r;
}
// fp8 x fp8 -> fp16 accumulators
__device__ __forceinline__ void mma_f8h(uint32_t d[2], const uint32_t a[4],
                                        uint32_t b0, uint32_t b1) {
    asm volatile(
        "mma.sync.aligned.m16n8k32.row.col.f16.e4m3.e4m3.f16 "
        "{%0,%1},{%2,%3,%4,%5},{%6,%7},{%0,%1};"
        : "+r"(d[0]), "+r"(d[1])
        : "r"(a[0]), "r"(a[1]), "r"(a[2]), "r"(a[3]), "r"(b0), "r"(b1));
}
#define LDMX4(r0, r1, r2, r3, addr)                                          \
    asm volatile("ldmatrix.sync.aligned.m8n8.x4.shared.b16 {%0,%1,%2,%3},[%4];" \
                 : "=r"(r0), "=r"(r1), "=r"(r2), "=r"(r3) : "r"(addr))

// ---------------- fp8 conversion ----------------
__global__ void convert_w8(const float* __restrict__ src) {
    size_t i = ((size_t)blockIdx.x * blockDim.x + threadIdx.x) * 16;
    const float4* s = reinterpret_cast<const float4*>(src + i);
    float4 f0 = s[0], f1 = s[1], f2 = s[2], f3 = s[3];
    uint32_t u0 = (uint32_t)cvt2_e4m3(f0.x * SW_W, f0.y * SW_W) |
                  ((uint32_t)cvt2_e4m3(f0.z * SW_W, f0.w * SW_W) << 16);
    uint32_t u1 = (uint32_t)cvt2_e4m3(f1.x * SW_W, f1.y * SW_W) |
                  ((uint32_t)cvt2_e4m3(f1.z * SW_W, f1.w * SW_W) << 16);
    uint32_t u2 = (uint32_t)cvt2_e4m3(f2.x * SW_W, f2.y * SW_W) |
                  ((uint32_t)cvt2_e4m3(f2.z * SW_W, f2.w * SW_W) << 16);
    uint32_t u3 = (uint32_t)cvt2_e4m3(f3.x * SW_W, f3.y * SW_W) |
                  ((uint32_t)cvt2_e4m3(f3.z * SW_W, f3.w * SW_W) << 16);
    *reinterpret_cast<uint4*>(g_W8 + i) = make_uint4(u0, u1, u2, u3);
}
__global__ void convert_x8(const float* __restrict__ src) {
    size_t i = ((size_t)blockIdx.x * blockDim.x + threadIdx.x) * 16;
    const float4* s = reinterpret_cast<const float4*>(src + i);
    float4 f0 = s[0], f1 = s[1], f2 = s[2], f3 = s[3];
    uint32_t u0 = (uint32_t)cvt2_e4m3(f0.x * SW_X, f0.y * SW_X) |
                  ((uint32_t)cvt2_e4m3(f0.z * SW_X, f0.w * SW_X) << 16);
    uint32_t u1 = (uint32_t)cvt2_e4m3(f1.x * SW_X, f1.y * SW_X) |
                  ((uint32_t)cvt2_e4m3(f1.z * SW_X, f1.w * SW_X) << 16);
    uint32_t u2 = (uint32_t)cvt2_e4m3(f2.x * SW_X, f2.y * SW_X) |
                  ((uint32_t)cvt2_e4m3(f2.z * SW_X, f2.w * SW_X) << 16);
    uint32_t u3 = (uint32_t)cvt2_e4m3(f3.x * SW_X, f3.y * SW_X) |
                  ((uint32_t)cvt2_e4m3(f3.z * SW_X, f3.w * SW_X) << 16);
    *reinterpret_cast<uint4*>(g_X8 + i) = make_uint4(u0, u1, u2, u3);
}

// ---------------- target score (exact fp32) ----------------
__global__ void target_score_kernel(const float* __restrict__ x,
                                    const float* __restrict__ w,
                                    const int* __restrict__ target) {
    int t = blockIdx.x * 8 + (threadIdx.x >> 5);
    int lane = threadIdx.x & 31;
    if (t >= TOKENS) return;
    int tgt = target[t];
    const float4* xr = reinterpret_cast<const float4*>(x + (size_t)t * DMODEL);
    const float4* wr = reinterpret_cast<const float4*>(w + (size_t)tgt * DMODEL);
    float s = 0.0f;
    #pragma unroll
    for (int i = lane; i < DMODEL / 4; i += 32) {
        float4 a = xr[i]; float4 b = wr[i];
        s += a.x * b.x + a.y * b.y + a.z * b.z + a.w * b.w;
    }
    #pragma unroll
    for (int o = 16; o; o >>= 1) s += __shfl_xor_sync(0xffffffffu, s, o);
    if (lane == 0) g_ts[t] = s;
}

// B-chunk producer: chunk c -> stage st. 128 rows x 128 B, swizzled.
// Per thread: rows (tid>>3) and (tid>>3)+64, granule tid&7.
__device__ __forceinline__ void issue_b(int c, int st, const uint8_t* src_base,
                                        uint32_t dst_base) {
    const uint8_t* src = src_base + (size_t)(c >> 2) * (NSPLITS * BN * DMODEL)
                       + (c & 3) * BK;
    uint32_t dst = dst_base + (uint32_t)(st * BSTAGE);
    asm volatile("cp.async.cg.shared.global [%0], [%1], 16;\n"
                 :: "r"(dst), "l"(src));
    asm volatile("cp.async.cg.shared.global [%0], [%1], 16;\n"
                 :: "r"(dst + 64 * 128), "l"(src + (size_t)64 * DMODEL));
    asm volatile("cp.async.commit_group;\n" ::: "memory");
}

// ---------------- main CE partial kernel (fp8 f16-acc, 6-stage swizzled ring) ------
__global__ void __launch_bounds__(512, 1) ce8_kernel() {
    extern __shared__ char smem[];
    const int tid = threadIdx.x;
    const int lane = tid & 31;
    const int wid = tid >> 5;
    const int wm = wid >> 1;             // 0..7 : m-rows [wm*32, wm*32+32)
    const int wn = wid & 1;              // 0..1 : n-cols [wn*64, wn*64+64)
    const int tile_m = blockIdx.x;
    const int split  = blockIdx.y;

    const uint32_t As_u = (uint32_t)__cvta_generic_to_shared(smem);
    const uint32_t Bs_u = As_u + A_BYTES;
    float* red = reinterpret_cast<float*>(smem + RED_OFF);

    // ---- A tile: 256 x 512 fp8, swizzled, loaded once ----
    {
        const uint8_t* src = g_X8 + (size_t)tile_m * (BM * DMODEL);
        #pragma unroll
        for (int it = 0; it < 16; ++it) {
            int ch = tid + it * 512;      // 8192 granules of 16B, 32 per row
            int row = ch >> 5, c16 = ch & 31;
            uint32_t sa = As_u + (uint32_t)(row * 512 + ((c16 * 16) ^ ((row & 7) << 4)));
            const void* g = (const void*)(src + (size_t)row * DMODEL + c16 * 16);
            asm volatile("cp.async.cg.shared.global [%0], [%1], 16;\n" :: "r"(sa), "l"(g));
        }
        asm volatile("cp.async.commit_group;\n" ::: "memory");
    }

    const int ntile_cnt = (NTILES_N - 1 - split) / NSPLITS + 1;  // 27 or 28
    const int NP = ntile_cnt * 2;        // pairs of 128B chunks

    // per-thread producer addressing (hoisted, swizzled)
    {
        // nothing extra; folded below
    }
    const int prow = tid >> 3;
    const uint8_t* bsrc_base = g_W8 + (size_t)split * (BN * DMODEL)
                             + (size_t)prow * DMODEL + (tid & 7) * 16;
    const uint32_t bdst_base = Bs_u +
        (uint32_t)(prow * 128 + (((tid & 7) * 16) ^ ((prow & 7) << 4)));

    issue_b(0, 0, bsrc_base, bdst_base);
    issue_b(1, 1, bsrc_base, bdst_base);
    issue_b(2, 2, bsrc_base, bdst_base);
    issue_b(3, 3, bsrc_base, bdst_base);

    float rs[4];                          // (mi, row-half) exp-sum partials
    #pragma unroll
    for (int i = 0; i < 4; ++i) rs[i] = 0.0f;

    uint32_t acc[2][8][2];                // mi x n8-group x 2 f16x2 regs (m32 x n64)

    // ldmatrix addressing: per-lane fixed row -> fixed swizzle XOR
    const int arow = wm * 32 + (lane & 15);
    const uint32_t a_xr = (uint32_t)((arow & 7) << 4);
    const uint32_t a_csel = (uint32_t)(((lane >> 4) & 1) * 16);
    const uint32_t a_base0 = As_u + (uint32_t)(arow * 512);          // mi=0
    const uint32_t a_base1 = a_base0 + 16 * 512;                     // mi=1 (same xr)

    const int brow = wn * 64 + ((lane >> 4) & 1) * 8 + (lane & 7);
    const uint32_t b_xr = (uint32_t)((brow & 7) << 4);
    const uint32_t b_csel = (uint32_t)(((lane >> 3) & 1) * 16);
    const uint32_t b_base = Bs_u + (uint32_t)(brow * 128);

    int s0 = 0;                           // stage of chunk 2p

    for (int p = 0; p < NP; ++p) {
        if (p + 1 < NP) asm volatile("cp.async.wait_group 2;\n" ::: "memory");
        else            asm volatile("cp.async.wait_group 0;\n" ::: "memory");
        __syncthreads();

        const int kc0 = (2 * p) & 3;      // 0 or 2
        if (kc0 == 0) {
            #pragma unroll
            for (int mi = 0; mi < 2; ++mi)
                #pragma unroll
                for (int g = 0; g < 8; ++g) {
                    acc[mi][g][0] = 0u; acc[mi][g][1] = 0u;
                }
        }

        #pragma unroll
        for (int h = 0; h < 2; ++h) {     // two chunks per barrier
            const int kc = kc0 + h;
            const bool fin = (kc == 3);
            const uint32_t bstg = b_base + (uint32_t)((s0 + h) * BSTAGE);
            #pragma unroll
            for (int ks = 0; ks < 4; ++ks) {  // four k32 steps per 128B chunk
                uint32_t a0[4], a1[4];
                const uint32_t aoff =
                    ((uint32_t)(kc * BK + ks * 32) + a_csel) ^ a_xr;
                LDMX4(a0[0], a0[1], a0[2], a0[3], a_base0 + aoff);
                LDMX4(a1[0], a1[1], a1[2], a1[3], a_base1 + aoff);
                const uint32_t boff = ((uint32_t)(ks * 32) + b_csel) ^ b_xr;
                #pragma unroll
                for (int ng = 0; ng < 4; ++ng) {  // 4 n16 groups
                    uint32_t b0, b1, b2, b3;
                    LDMX4(b0, b1, b2, b3, bstg + (uint32_t)(ng * 16 * 128) + boff);
                    mma_f8h(acc[0][ng * 2 + 0], a0, b0, b1);
                    mma_f8h(acc[0][ng * 2 + 1], a0, b2, b3);
                    mma_f8h(acc[1][ng * 2 + 0], a1, b0, b1);
                    mma_f8h(acc[1][ng * 2 + 1], a1, b2, b3);
                    if (ks == 3 && fin) {
                        // final acc groups: fold exp now, overlapping MUFU with
                        // the remaining groups' MMA stream
                        #pragma unroll
                        for (int mi = 0; mi < 2; ++mi) {
                            #pragma unroll
                            for (int g = ng * 2; g < ng * 2 + 2; ++g) {
                                float2 v0 = __half22float2(
                                    *reinterpret_cast<__half2*>(&acc[mi][g][0]));
                                float2 v1 = __half22float2(
                                    *reinterpret_cast<__half2*>(&acc[mi][g][1]));
                                rs[mi * 2 + 0] += ex2f(v0.x * EPI_SCALE)
                                                + ex2f(v0.y * EPI_SCALE);
                                rs[mi * 2 + 1] += ex2f(v1.x * EPI_SCALE)
                                                + ex2f(v1.y * EPI_SCALE);
                            }
                        }
                    }
                }
            }
        }

        // issue next pair (chunks 2p+4, 2p+5) into stages (s0+4)%6, (s0+5)%6
        if (p + 2 < NP) {
            int c = 2 * p + 4;
            int st = s0 + 4; if (st >= NSTAGE) st -= NSTAGE;
            issue_b(c, st, bsrc_base, bdst_base);
            int st2 = st + 1; if (st2 >= NSTAGE) st2 -= NSTAGE;
            issue_b(c + 1, st2, bsrc_base, bdst_base);
        }
        s0 += 2; if (s0 >= NSTAGE) s0 -= NSTAGE;
    }

    // ---- reduce: quad (n within warp) -> smem (across the 2 n-warps) ----
    #pragma unroll
    for (int i = 0; i < 4; ++i) {
        rs[i] += __shfl_xor_sync(0xffffffffu, rs[i], 1);
        rs[i] += __shfl_xor_sync(0xffffffffu, rs[i], 2);
    }
    __syncthreads();
    if ((lane & 3) == 0) {
        int g = lane >> 2;               // 0..7
        int row0 = wm * 32 + g;
        red[row0 * 2 + wn] = rs[0];
        red[(row0 + 8) * 2 + wn] = rs[1];
        red[(row0 + 16) * 2 + wn] = rs[2];
        red[(row0 + 24) * 2 + wn] = rs[3];
    }
    __syncthreads();
    if (tid < BM) {
        g_sum[split * TOKENS + tile_m * BM + tid] = red[tid * 2] + red[tid * 2 + 1];
    }
}

// ---------------- final loss reduce ----------------
__global__ void loss_kernel(float* __restrict__ out) {
    __shared__ float sm[256];
    float acc = 0.0f;
    for (int t = threadIdx.x; t < TOKENS; t += 256) {
        float S = 0.0f;
        #pragma unroll
        for (int s = 0; s < NSPLITS; ++s) S += g_sum[s * TOKENS + t];
        acc += logf(S) - g_ts[t];
    }
    sm[threadIdx.x] = acc;
    __syncthreads();
    #pragma unroll
    for (int o = 128; o; o >>= 1) {
        if (threadIdx.x < o) sm[threadIdx.x] += sm[threadIdx.x + o];
        __syncthreads();
    }
    if (threadIdx.x == 0) out[0] = sm[0];
}

// ---------------- launch ----------------
extern "C" void kernel_launch(void* const* d_in, const int* in_sizes, int n_in,
                              void* d_out, int out_size) {
    const float* x = (const float*)d_in[0];
    const float* w = (const float*)d_in[1];
    const int* target = (const int*)d_in[2];
    float* out = (float*)d_out;
    (void)in_sizes; (void)n_in; (void)out_size;

    cudaFuncSetAttribute(ce8_kernel, cudaFuncAttributeMaxDynamicSharedMemorySize,
                         SMEM_TOTAL);

    convert_w8<<<16000, 256>>>(w);                    // 16000*256*16 = 65,536,000
    convert_x8<<<512, 256>>>(x);                      // 512*256*16  =  2,097,152
    target_score_kernel<<<TOKENS / 8, 256>>>(x, w, target);
    ce8_kernel<<<dim3(MTILES, NSPLITS), 512, SMEM_TOTAL>>>();
    loss_kernel<<<1, 256>>>(out);
}